// round 17
// baseline (speedup 1.0000x reference)
#include <cuda_runtime.h>
#include <math.h>

// Problem constants
#define B_   4
#define H_   16
#define NF_  32
#define P_   16
#define M_   257          // P*P + 1
#define S_   (NF_ * M_)   // 8224
#define D_   64
#define NTOK (B_ * H_ * S_)   // 526336 tokens per tensor

// ---------------------------------------------------------------------------
// 256-bit global load/store (sm_100+ PTX .v8.f32), streaming (.cs) policy.
// ---------------------------------------------------------------------------
__device__ __forceinline__ void ldg256_cs(const float* p, float* v) {
    asm volatile("ld.global.cs.v8.f32 {%0,%1,%2,%3,%4,%5,%6,%7}, [%8];"
        : "=f"(v[0]), "=f"(v[1]), "=f"(v[2]), "=f"(v[3]),
          "=f"(v[4]), "=f"(v[5]), "=f"(v[6]), "=f"(v[7])
        : "l"(p));
}

__device__ __forceinline__ void stg256_cs(float* p, const float* v) {
    asm volatile("st.global.cs.v8.f32 [%0], {%1,%2,%3,%4,%5,%6,%7,%8};"
        :: "l"(p),
           "f"(v[0]), "f"(v[1]), "f"(v[2]), "f"(v[3]),
           "f"(v[4]), "f"(v[5]), "f"(v[6]), "f"(v[7])
        : "memory");
}

// ---------------------------------------------------------------------------
// Pure-fp32 sincos for |x| <= ~403 rad. Cody-Waite: 2*pi = C0 + C1, with
// C0 = 6.28125 (k*C0 exact for k <= 64), C1 = 2*pi - C0. Then MUFU
// __sinf/__cosf on [-pi, pi] (abs err ~4e-7; gate is 1e-3).
// ---------------------------------------------------------------------------
__device__ __forceinline__ float2 fast_cs(float f) {
    const float INV_2PI = 0.15915494309189533f;
    const float C0 = 6.28125f;
    const float C1 = 1.9353071795864769e-3f;
    float kf = rintf(f * INV_2PI);
    float r  = fmaf(-kf, C0, f);
    r        = fmaf(-kf, C1, r);
    return make_float2(__cosf(r), __sinf(r));
}

// Freq element index for pair p at grid cell (frame, r, c).
// freqs shape (32,17,17,30): dims [0,10) depend on frame, [10,20) on r,
// [20,30) on c; adjacent dims repeat. ~330 distinct addresses, L1-resident.
__device__ __forceinline__ int freq_idx(int p, int frame, int r, int c) {
    if (p < 5)  return frame * (17 * 17 * 30) + 2 * p;
    if (p < 10) return r * (17 * 30) + 10 + 2 * (p - 5);
    return c * 30 + 20 + 2 * (p - 10);
}

// ---------------------------------------------------------------------------
// 256-bit variant: 4 threads per seq-position. Thread tt handles floats
// [8tt, 8tt+8) (rotated; pairs 4tt..4tt+3, pair 15 = identity) and floats
// [32+8tt, 32+8tt+8) (copy) of BOTH q and k at the same (b,h,s).
// 4 x 32B loads + 4 x 32B stores per thread: halves LDG/STG issue count and
// L1tex wavefronts vs the 128-bit version. cos/sin inline, amortized q+k.
// ---------------------------------------------------------------------------
__global__ __launch_bounds__(256) void frame_rope_kernel(
        const float*  __restrict__ freqs,
        const float*  __restrict__ q,
        const float*  __restrict__ k,
        float*        __restrict__ out) {
    int gid = blockIdx.x * blockDim.x + threadIdx.x;   // < NTOK*4
    int tt  = gid & 3;          // 32B chunk id within rotated half (0..3)
    int tok = gid >> 2;         // token id (same for q and k)

    const float* qb = q + tok * 64;
    const float* kb = k + tok * 64;
    int o0 = tt * 8;            // rotated chunk offset (floats)
    int o1 = 32 + tt * 8;       // copy chunk offset

    // Front-batch all four independent 256-bit streaming loads.
    float q0[8], q1[8], k0[8], k1[8];
    ldg256_cs(qb + o0, q0);
    ldg256_cs(qb + o1, q1);
    ldg256_cs(kb + o0, k0);
    ldg256_cs(kb + o1, k1);

    // Position -> (frame, r, c); audio token (m==256) -> cell (16,16).
    int s     = tok % S_;
    int frame = s / M_;
    int m     = s - frame * M_;
    int r, c;
    if (m == 256) { r = 16; c = 16; }
    else          { r = m >> 4; c = m & 15; }

    // Pairs p = 4*tt + j, j = 0..3; p == 15 -> identity (dims 30,31).
    float oq[8], ok[8];
#pragma unroll
    for (int j = 0; j < 4; j++) {
        int p = 4 * tt + j;
        float2 cs;
        if (p < 15) {
            float f = __ldg(freqs + freq_idx(p, frame, r, c));
            cs = fast_cs(f);
        } else {
            cs = make_float2(1.0f, 0.0f);
        }
        float a = q0[2 * j], b = q0[2 * j + 1];
        oq[2 * j]     = a * cs.x - b * cs.y;
        oq[2 * j + 1] = b * cs.x + a * cs.y;
        float e = k0[2 * j], g = k0[2 * j + 1];
        ok[2 * j]     = e * cs.x - g * cs.y;
        ok[2 * j + 1] = g * cs.x + e * cs.y;
    }

    float* oqb = out + tok * 64;
    float* okb = out + (NTOK + tok) * 64;
    stg256_cs(oqb + o0, oq);
    stg256_cs(oqb + o1, q1);
    stg256_cs(okb + o0, ok);
    stg256_cs(okb + o1, k1);
}

extern "C" void kernel_launch(void* const* d_in, const int* in_sizes, int n_in,
                              void* d_out, int out_size) {
    const float* q     = (const float*)d_in[0];
    const float* k     = (const float*)d_in[1];
    const float* freqs = (const float*)d_in[2];

    const int total_threads = NTOK * 4;   // 2,105,344 -> 8,224 blocks of 256
    frame_rope_kernel<<<total_threads / 256, 256>>>(
        freqs, q, k, (float*)d_out);
}